// round 16
// baseline (speedup 1.0000x reference)
#include <cuda_runtime.h>
#include <cuda_fp16.h>
#include <math.h>
#include <stdint.h>

// Problem constants
#define T_ALL 16
#define B_    32
#define C_    256
#define HW    256
#define KLAG  4
#define TQ    12
#define CHW   (C_ * HW)          // 65536
#define BCHW  (B_ * CHW)         // 2097152
#define NPAIR (TQ * B_)          // 384

// Output layout (float32)
#define SPK_N    (T_ALL * BCHW)
#define OUT_LOSS (SPK_N)
#define OUT_LSP  (SPK_N + 1)
#define OUT_LSN  (SPK_N + 1 + NPAIR)

// Role split: per tq, bs in [0,21) -> mma role, bs in [21,32) -> popc role.
#define MMA_BS   21
#define POPC_BS  (B_ - MMA_BS)                 // 11
#define N_MMA    (TQ * MMA_BS * 8)             // 2016 CTAs
#define N_POPC   (TQ * POPC_BS * 2)            // 264 CTAs
#define GRID_N   (N_POPC * 9)                  // 2376 (1-in-9 popc)

// Bit planes: [t][b][c][8 words]; consistent packed-hw permutation everywhere.
#define NWORDS (TQ * BCHW / 32)
__device__ unsigned g_ctxb[NWORDS];
__device__ unsigned g_spkb[NWORDS];
__device__ __half   g_w16[C_ * C_];      // fp16 copy of W
__device__ float    g_ppos[NPAIR * 8];   // [pair][slot]
__device__ float    g_pneg[NPAIR * 8];

// ---------------------------------------------------------------------------
// 1) Fused copy + LIF scan + bitpack; blocks 0..63 also convert W -> fp16.
// ---------------------------------------------------------------------------
__global__ __launch_bounds__(256)
void scan_kernel(const float4* __restrict__ spk, float4* __restrict__ out,
                 const float4* __restrict__ Wg) {
    const int i    = blockIdx.x * 256 + threadIdx.x;   // 0 .. BCHW/4-1
    const int lane = threadIdx.x & 31;
    const int row   = i >> 6;
    const int wbase = row * 8 + ((i & 63) >> 5) * 4;

    float m0 = 0.f, m1 = 0.f, m2 = 0.f, m3 = 0.f;
#pragma unroll
    for (int t = 0; t < T_ALL; t++) {
        float4 v = spk[t * (BCHW / 4) + i];
        out[t * (BCHW / 4) + i] = v;
        float r0 = (m0 > 1.f) ? 1.f : 0.f;
        float r1 = (m1 > 1.f) ? 1.f : 0.f;
        float r2 = (m2 > 1.f) ? 1.f : 0.f;
        float r3 = (m3 > 1.f) ? 1.f : 0.f;
        m0 = 0.5f * m0 + v.x - r0;
        m1 = 0.5f * m1 + v.y - r1;
        m2 = 0.5f * m2 + v.z - r2;
        m3 = 0.5f * m3 + v.w - r3;
        if (t >= KLAG) {
            unsigned b0 = __ballot_sync(0xFFFFFFFFu, v.x > 0.5f);
            unsigned b1 = __ballot_sync(0xFFFFFFFFu, v.y > 0.5f);
            unsigned b2 = __ballot_sync(0xFFFFFFFFu, v.z > 0.5f);
            unsigned b3 = __ballot_sync(0xFFFFFFFFu, v.w > 0.5f);
            if (lane == 0) {
                unsigned* p = &g_spkb[(t - KLAG) * (BCHW / 32) + wbase];
                p[0] = b0; p[1] = b1; p[2] = b2; p[3] = b3;
            }
        }
        if (t < TQ) {
            unsigned c0 = __ballot_sync(0xFFFFFFFFu, m0 > 1.f);
            unsigned c1 = __ballot_sync(0xFFFFFFFFu, m1 > 1.f);
            unsigned c2 = __ballot_sync(0xFFFFFFFFu, m2 > 1.f);
            unsigned c3 = __ballot_sync(0xFFFFFFFFu, m3 > 1.f);
            if (lane == 0) {
                unsigned* p = &g_ctxb[t * (BCHW / 32) + wbase];
                p[0] = c0; p[1] = c1; p[2] = c2; p[3] = c3;
            }
        }
    }
    // W -> fp16 (65536 elems = 16384 float4, blocks 0..63)
    if (blockIdx.x < 64) {
        int idx = blockIdx.x * 256 + threadIdx.x;      // 0..16383
        float4 w = Wg[idx];
        __half2 lo = __floats2half2_rn(w.x, w.y);
        __half2 hi = __floats2half2_rn(w.z, w.w);
        *(uint2*)&g_w16[idx * 4] =
            make_uint2(*(uint32_t*)&lo, *(uint32_t*)&hi);
    }
}

// ---------------------------------------------------------------------------
// 2) Hybrid kernel: mma-role CTAs (f16 HMMA X-GEMM, R11-validated) interleaved
//    with popc-role CTAs (exact AND+POPC, R4-validated, restructured ownership).
// ---------------------------------------------------------------------------
#define PITCH 272                       // 128 fp16 (256 B) + 16 B pad
#define OFF_BNEG  0
#define OFF_RED   16                    // 16 floats
#define OFF_STAGE 128                   // 1024 u32 = 4096 B
#define OFF_MASKP 4224                  // 512 u32
#define OFF_MASKN 6272                  // 512 u32
#define OFF_A     8320                  // 128 x 272 = 34816
#define OFF_B     43136                 // 128 x 272 = 34816
#define SMEM_TOTAL 77952
// popc-role layout (within the same dynamic smem block)
#define POFF_CTXP 0                     // 1024 u32 = 4096 B
#define POFF_CTXN 4096                  // 1024 u32
#define POFF_BNEG 8192
#define POFF_RED  8256                  // 16 floats

__device__ __forceinline__ uint32_t smem_u32(const void* p) {
    uint32_t a;
    asm("{ .reg .u64 t; cvta.to.shared.u64 t, %1; cvt.u32.u64 %0, t; }" : "=r"(a) : "l"(p));
    return a;
}
__device__ __forceinline__ void cp16(uint32_t dst, const void* src) {
    asm volatile("cp.async.cg.shared.global [%0], [%1], 16;"
                 :: "r"(dst), "l"(src) : "memory");
}
__device__ __forceinline__ void ldsm4(uint32_t addr, uint32_t& r0, uint32_t& r1,
                                      uint32_t& r2, uint32_t& r3) {
    asm volatile("ldmatrix.sync.aligned.m8n8.x4.shared.b16 {%0,%1,%2,%3}, [%4];"
                 : "=r"(r0), "=r"(r1), "=r"(r2), "=r"(r3) : "r"(addr));
}
__device__ __forceinline__ void mma_f16(float* c, const uint32_t* a, const uint32_t* b) {
    asm volatile(
        "mma.sync.aligned.m16n8k16.row.col.f32.f16.f16.f32 "
        "{%0,%1,%2,%3}, {%4,%5,%6,%7}, {%8,%9}, {%0,%1,%2,%3};"
        : "+f"(c[0]), "+f"(c[1]), "+f"(c[2]), "+f"(c[3])
        : "r"(a[0]), "r"(a[1]), "r"(a[2]), "r"(a[3]), "r"(b[0]), "r"(b[1]));
}

__global__ __launch_bounds__(256, 2)
void work_kernel(const float* __restrict__ Wg, const int* __restrict__ ridx) {
    extern __shared__ char smem[];
    const int tid = threadIdx.x, wid = tid >> 5, lane = tid & 31;
    const int g = blockIdx.x / 9, r = blockIdx.x % 9;

    if (r == 8) {
        // =================== popc role (exact) ===================
        const int popc_id = g;                   // 0..263
        const int pairh = popc_id >> 1, oh = popc_id & 1;
        const int tq = pairh / POPC_BS;
        const int bs = MMA_BS + pairh % POPC_BS; // 21..31
        unsigned* ctxP = (unsigned*)(smem + POFF_CTXP);
        unsigned* ctxN = (unsigned*)(smem + POFF_CTXN);
        float*    red  = (float*)(smem + POFF_RED);

        if (tid < 32 && ridx[tid] == bs) *(int*)(smem + POFF_BNEG) = tid;

        // S rows in regs: thread = c column
        const uint4* sp4 = (const uint4*)
            (g_spkb + ((size_t)(tq * B_ + bs) * C_ + tid) * 8);
        uint4 s0 = sp4[0], s1 = sp4[1];

        // ctxP rows (this oh half): 256 uint4
        {
            int rw = tid >> 1, hf = tid & 1;
            const uint4* cp = (const uint4*)
                (g_ctxb + ((size_t)(tq * B_ + bs) * C_ + oh * 128 + rw) * 8 + hf * 4);
            ((uint4*)ctxP)[tid] = cp[0];
        }
        __syncthreads();
        const int bneg = *(const int*)(smem + POFF_BNEG);
        {
            int rw = tid >> 1, hf = tid & 1;
            const uint4* cn = (const uint4*)
                (g_ctxb + ((size_t)(tq * B_ + bneg) * C_ + oh * 128 + rw) * 8 + hf * 4);
            ((uint4*)ctxN)[tid] = cn[0];
        }
        __syncthreads();

        float accp = 0.f, accn = 0.f;
        const float* wcol = Wg + (size_t)(oh * 128) * C_ + tid;
#pragma unroll 4
        for (int o = 0; o < 128; o++) {
            uint4 c0 = ((const uint4*)ctxP)[o * 2];
            uint4 c1 = ((const uint4*)ctxP)[o * 2 + 1];
            int mp = __popc(c0.x & s0.x) + __popc(c0.y & s0.y)
                   + __popc(c0.z & s0.z) + __popc(c0.w & s0.w)
                   + __popc(c1.x & s1.x) + __popc(c1.y & s1.y)
                   + __popc(c1.z & s1.z) + __popc(c1.w & s1.w);
            uint4 d0 = ((const uint4*)ctxN)[o * 2];
            uint4 d1 = ((const uint4*)ctxN)[o * 2 + 1];
            int mn = __popc(d0.x & s0.x) + __popc(d0.y & s0.y)
                   + __popc(d0.z & s0.z) + __popc(d0.w & s0.w)
                   + __popc(d1.x & s1.x) + __popc(d1.y & s1.y)
                   + __popc(d1.z & s1.z) + __popc(d1.w & s1.w);
            float w = __ldg(&wcol[(size_t)o * C_]);
            accp += w * (float)mp;
            accn += w * (float)mn;
        }

#pragma unroll
        for (int off = 16; off > 0; off >>= 1) {
            accp += __shfl_down_sync(0xFFFFFFFFu, accp, off);
            accn += __shfl_down_sync(0xFFFFFFFFu, accn, off);
        }
        if (lane == 0) { red[wid] = accp; red[8 + wid] = accn; }
        __syncthreads();
        if (tid == 0) {
            float sp = 0.f, sn = 0.f;
#pragma unroll
            for (int w = 0; w < 8; w++) { sp += red[w]; sn += red[8 + w]; }
            float* pp = &g_ppos[((size_t)tq * B_ + bs) * 8];
            float* pn = &g_pneg[((size_t)tq * B_ + bneg) * 8];
            pp[oh] = sp; pp[oh + 2] = 0.f; pp[oh + 4] = 0.f; pp[oh + 6] = 0.f;
            pn[oh] = sn; pn[oh + 2] = 0.f; pn[oh + 4] = 0.f; pn[oh + 6] = 0.f;
        }
        return;
    }

    // =================== mma role (R11-validated body) ===================
    const int mma_id = g * 8 + r;
    if (mma_id >= N_MMA) return;
    const int slot = mma_id & 7;
    const int kh = slot & 1, nh = (slot >> 1) & 1, oh = slot >> 2;
    const int pair_lin = mma_id >> 3;          // 0..251
    const int tq = pair_lin / MMA_BS;
    const int bs = pair_lin % MMA_BS;          // 0..20

    const uint32_t sb = smem_u32(smem);
    unsigned* stage = (unsigned*)(smem + OFF_STAGE);
    unsigned* maskP = (unsigned*)(smem + OFF_MASKP);
    unsigned* maskN = (unsigned*)(smem + OFF_MASKN);
    float*    red   = (float*)(smem + OFF_RED);

    // inverse permutation
    if (tid < 32 && ridx[tid] == bs) *(int*)(smem + OFF_BNEG) = tid;
    __syncthreads();
    const int bneg = *(const int*)(smem + OFF_BNEG);

    // Stage spk bit words for this kh half (1024 words)
    {
        const uint4* src = (const uint4*)
            (g_spkb + ((size_t)(tq * B_ + bs) * C_ + kh * 128) * 8);
        ((uint4*)stage)[tid & 255] = src[tid];
    }
    // Masks: rows o in oh-half, words wi in nh-half (4 per row)
    {
        if (tid < 128) {
            const uint4* mp = (const uint4*)
                (g_ctxb + ((size_t)(tq * B_ + bs) * C_ + oh * 128 + tid) * 8 + nh * 4);
            ((uint4*)maskP)[tid] = mp[0];
        } else {
            int rr = tid - 128;
            const uint4* mn = (const uint4*)
                (g_ctxb + ((size_t)(tq * B_ + bneg) * C_ + oh * 128 + rr) * 8 + nh * 4);
            ((uint4*)maskN)[rr] = mn[0];
        }
    }
    // A tile via cp.async: W[oh*128 + m][kh*128 + k] fp16, 16B chunks
    {
#pragma unroll
        for (int q = 0; q < 8; q++) {
            int idx = q * 256 + tid;            // 0..2047
            int rr = idx >> 4, ch = idx & 15;
            cp16(sb + OFF_A + rr * PITCH + ch * 16,
                 (const char*)g_w16 + ((size_t)(oh * 128 + rr) * C_ + kh * 128) * 2 + ch * 16);
        }
        asm volatile("cp.async.commit_group;" ::: "memory");
    }
    __syncthreads();   // stage visible

    // Expand B tile: row n (packed hw, nh half), cols k (c local, kh half).
    {
        const int rloc = tid >> 1;              // 0..127
        const int half = tid & 1;               // k-half of the row
        const int w    = nh * 4 + (rloc >> 5);  // ctx/spk word index
        const int bit  = rloc & 31;
        char* brow = smem + OFF_B + rloc * PITCH + half * 128;
#pragma unroll
        for (int c8 = 0; c8 < 8; c8++) {
            int cb = half * 64 + c8 * 8;
            uint32_t h[4];
#pragma unroll
            for (int j = 0; j < 4; j++) {
                unsigned b0 = (stage[(cb + 2 * j) * 8 + w] >> bit) & 1u;
                unsigned b1 = (stage[(cb + 2 * j + 1) * 8 + w] >> bit) & 1u;
                h[j] = (b0 ? 0x3C00u : 0u) | (b1 ? 0x3C000000u : 0u);
            }
            *(uint4*)(brow + c8 * 16) = make_uint4(h[0], h[1], h[2], h[3]);
        }
    }
    asm volatile("cp.async.wait_group 0;" ::: "memory");
    __syncthreads();

    // Mainloop: warp grid 2(m) x 4(n); warp tile 64m x 32n; K = 128 (8 steps)
    const int warpM = wid >> 2, warpN = wid & 3;
    float acc[4][4][4];
#pragma unroll
    for (int mi = 0; mi < 4; mi++)
#pragma unroll
        for (int ni = 0; ni < 4; ni++)
#pragma unroll
            for (int e = 0; e < 4; e++) acc[mi][ni][e] = 0.f;

    const uint32_t aBase = sb + OFF_A;
    const uint32_t bBase = sb + OFF_B;
    const int lrow = lane & 15, lcol = (lane >> 4) * 16;

#pragma unroll
    for (int k0 = 0; k0 < 8; k0++) {
        uint32_t a[4][4], b[4][2];
#pragma unroll
        for (int mi = 0; mi < 4; mi++) {
            uint32_t addr = aBase + (warpM * 64 + mi * 16 + lrow) * PITCH
                          + k0 * 32 + lcol;
            ldsm4(addr, a[mi][0], a[mi][1], a[mi][2], a[mi][3]);
        }
#pragma unroll
        for (int nb = 0; nb < 2; nb++) {
            uint32_t addr = bBase + (warpN * 32 + nb * 16 + lrow) * PITCH
                          + k0 * 32 + lcol;
            uint32_t r0, r1, r2, r3;
            ldsm4(addr, r0, r1, r2, r3);
            b[nb * 2 + 0][0] = r0; b[nb * 2 + 0][1] = r2;
            b[nb * 2 + 1][0] = r1; b[nb * 2 + 1][1] = r3;
        }
#pragma unroll
        for (int mi = 0; mi < 4; mi++)
#pragma unroll
            for (int ni = 0; ni < 4; ni++)
                mma_f16(acc[mi][ni], a[mi], b[ni]);
    }

    // Epilogue: masked adds (pos & neg) using local masks
    float accp = 0.f, accn = 0.f;
    const int rl = lane >> 2, cl = (lane & 3) << 1;
#pragma unroll
    for (int mi = 0; mi < 4; mi++) {
        int r0 = warpM * 64 + mi * 16 + rl;
        int r1 = r0 + 8;
#pragma unroll
        for (int ni = 0; ni < 4; ni++) {
            int nl = warpN * 32 + ni * 8 + cl;     // 0..127
            int wi = nl >> 5, sh = nl & 31;
            unsigned p0 = maskP[r0 * 4 + wi] >> sh;
            unsigned p1 = maskP[r1 * 4 + wi] >> sh;
            unsigned n0 = maskN[r0 * 4 + wi] >> sh;
            unsigned n1 = maskN[r1 * 4 + wi] >> sh;
            float* c = acc[mi][ni];
            accp += ((p0 & 1u) ? c[0] : 0.f) + ((p0 & 2u) ? c[1] : 0.f)
                  + ((p1 & 1u) ? c[2] : 0.f) + ((p1 & 2u) ? c[3] : 0.f);
            accn += ((n0 & 1u) ? c[0] : 0.f) + ((n0 & 2u) ? c[1] : 0.f)
                  + ((n1 & 1u) ? c[2] : 0.f) + ((n1 & 2u) ? c[3] : 0.f);
        }
    }

#pragma unroll
    for (int off = 16; off > 0; off >>= 1) {
        accp += __shfl_down_sync(0xFFFFFFFFu, accp, off);
        accn += __shfl_down_sync(0xFFFFFFFFu, accn, off);
    }
    if (lane == 0) { red[wid] = accp; red[8 + wid] = accn; }
    __syncthreads();
    if (tid == 0) {
        float sp = 0.f, sn = 0.f;
#pragma unroll
        for (int w = 0; w < 8; w++) { sp += red[w]; sn += red[8 + w]; }
        g_ppos[((size_t)tq * B_ + bs)   * 8 + slot] = sp;
        g_pneg[((size_t)tq * B_ + bneg) * 8 + slot] = sn;
    }
}

// ---------------------------------------------------------------------------
// 3) Finalize
// ---------------------------------------------------------------------------
__global__ void finalize_kernel(float* __restrict__ out) {
    __shared__ float s_neg[TQ][B_];
    __shared__ float s_lsp[NPAIR];
    __shared__ float s_lsn[TQ];
    int tid = threadIdx.x;
    int tq = tid >> 5, b = tid & 31;

    float sp = 0.f, sn = 0.f;
#pragma unroll
    for (int s = 0; s < 8; s++) {
        sp += g_ppos[tid * 8 + s];
        sn += g_pneg[tid * 8 + s];
    }
    float score_pos = expf(sp * (1.0f / (float)CHW)) + 1e-4f;
    float score_neg = expf(sn * (1.0f / (float)CHW)) + 1e-4f;
    float lsp = logf(score_pos);
    s_neg[tq][b] = score_neg;
    s_lsp[tid]   = lsp;
    out[OUT_LSP + tid] = lsp;
    __syncthreads();
    if (b == 0) {
        float s = 0.0f;
#pragma unroll
        for (int bb = 0; bb < B_; bb++) s += s_neg[tq][bb];
        float lsn = logf(s);
        s_lsn[tq] = lsn;
        out[OUT_LSN + tq] = lsn;
    }
    __syncthreads();
    if (tid == 0) {
        float a = 0.0f;
        for (int i = 0; i < NPAIR; i++) a += (-s_lsp[i] + s_lsn[i >> 5]);
        out[OUT_LOSS] = a * (1.0f / (float)NPAIR);
    }
}

// ---------------------------------------------------------------------------
extern "C" void kernel_launch(void* const* d_in, const int* in_sizes, int n_in,
                              void* d_out, int out_size) {
    const float* spk  = (const float*)d_in[0];
    const float* Wg   = (const float*)d_in[2];
    const int*   ridx = (const int*)d_in[3];
    float* out = (float*)d_out;

    static int configured = 0;
    if (!configured) {
        cudaFuncSetAttribute(work_kernel, cudaFuncAttributeMaxDynamicSharedMemorySize,
                             SMEM_TOTAL);
        configured = 1;
    }

    scan_kernel<<<BCHW / 4 / 256, 256>>>((const float4*)spk, (float4*)out,
                                         (const float4*)Wg);
    work_kernel<<<GRID_N, 256, SMEM_TOTAL>>>(Wg, ridx);
    finalize_kernel<<<1, NPAIR>>>(out);
}